// round 2
// baseline (speedup 1.0000x reference)
#include <cuda_runtime.h>

#define Bsz 16
#define Cch 512
#define HWs 4096
#define Lt  77
#define Dd  768
#define NHh 8
#define HDd 64

// ---------------- scratch (device globals; no allocation allowed) ----------------
__device__ float g_q[(size_t)Bsz * HWs * Cch];     // token-major [b][hw][c]; LN in place
__device__ float g_attn[(size_t)Bsz * HWs * Cch];  // attention output, token-major
__device__ float g_k[Bsz * Lt * Cch];              // token-major [b*l][c]; LN in place
__device__ float g_v[Bsz * Lt * Cch];

// =====================================================================
// KV projection (NT GEMM): out[m=token][n=c] = sum_d tf[m][d] * W[n][d] + bias[n]
// M=1232, N=512, K=768. grid (4, 10, 2) z: 0->k, 1->v. 128x128x16 tile.
// =====================================================================
__global__ __launch_bounds__(256) void kv_proj_kernel(
    const float* __restrict__ tf,
    const float* __restrict__ wk, const float* __restrict__ bk,
    const float* __restrict__ wv, const float* __restrict__ bv)
{
    const int M = Bsz * Lt;
    const float* W; const float* bias; float* out;
    if (blockIdx.z == 0) { W = wk; bias = bk; out = g_k; }
    else                 { W = wv; bias = bv; out = g_v; }

    __shared__ float As[16][132];
    __shared__ float Bs[16][132];
    const int m0 = blockIdx.y * 128, n0 = blockIdx.x * 128;
    const int tid = threadIdx.x;
    const int tx = tid & 15, ty = tid >> 4;
    float acc[8][8] = {};

    for (int k0 = 0; k0 < Dd; k0 += 16) {
        #pragma unroll
        for (int u = 0; u < 2; u++) {
            int f = tid + 256 * u;
            int r = f >> 2, kc = (f & 3) << 2;
            float4 a4 = make_float4(0.f, 0.f, 0.f, 0.f);
            if (m0 + r < M)
                a4 = *(const float4*)(tf + (size_t)(m0 + r) * Dd + k0 + kc);
            As[kc][r] = a4.x; As[kc + 1][r] = a4.y; As[kc + 2][r] = a4.z; As[kc + 3][r] = a4.w;
            float4 w4 = *(const float4*)(W + (size_t)(n0 + r) * Dd + k0 + kc);
            Bs[kc][r] = w4.x; Bs[kc + 1][r] = w4.y; Bs[kc + 2][r] = w4.z; Bs[kc + 3][r] = w4.w;
        }
        __syncthreads();
        #pragma unroll
        for (int kk = 0; kk < 16; kk++) {
            float a[8], bfr[8];
            *(float4*)(a)     = *(const float4*)&As[kk][ty * 8];
            *(float4*)(a + 4) = *(const float4*)&As[kk][ty * 8 + 4];
            *(float4*)(bfr)     = *(const float4*)&Bs[kk][tx * 8];
            *(float4*)(bfr + 4) = *(const float4*)&Bs[kk][tx * 8 + 4];
            #pragma unroll
            for (int i = 0; i < 8; i++)
                #pragma unroll
                for (int j = 0; j < 8; j++) acc[i][j] += a[i] * bfr[j];
        }
        __syncthreads();
    }
    #pragma unroll
    for (int i = 0; i < 8; i++) {
        int m = m0 + ty * 8 + i;
        if (m >= M) break;
        float* op = out + (size_t)m * Cch + n0 + tx * 8;
        #pragma unroll
        for (int j = 0; j < 8; j++) op[j] = acc[i][j] + bias[n0 + tx * 8 + j];
    }
}

// =====================================================================
// Q projection (NN GEMM) per batch: q[n=hw][m=o] = sum_c wq[m][c] * x[b][c][n]
//   + bq[m] + 0.05*pe(m,n).  M=512, N=4096, K=512. grid (32, 4, 16).
// Output written token-major for the LN / attention stages.
// =====================================================================
__global__ __launch_bounds__(256) void q_proj_kernel(
    const float* __restrict__ x, const float* __restrict__ wq, const float* __restrict__ bq)
{
    const int b = blockIdx.z;
    const float* X = x + (size_t)b * Cch * HWs;
    float* out = g_q + (size_t)b * HWs * Cch;

    __shared__ float As[16][132];
    __shared__ float Bs[16][128];
    const int m0 = blockIdx.y * 128, n0 = blockIdx.x * 128;
    const int tid = threadIdx.x;
    const int tx = tid & 15, ty = tid >> 4;
    float acc[8][8] = {};

    for (int k0 = 0; k0 < Cch; k0 += 16) {
        #pragma unroll
        for (int u = 0; u < 2; u++) {
            int f = tid + 256 * u;
            int r = f >> 2, kc = (f & 3) << 2;
            float4 a4 = *(const float4*)(wq + (size_t)(m0 + r) * Cch + k0 + kc);
            As[kc][r] = a4.x; As[kc + 1][r] = a4.y; As[kc + 2][r] = a4.z; As[kc + 3][r] = a4.w;
            int kk = f >> 5, nc = (f & 31) << 2;
            float4 b4 = *(const float4*)(X + (size_t)(k0 + kk) * HWs + n0 + nc);
            *(float4*)&Bs[kk][nc] = b4;
        }
        __syncthreads();
        #pragma unroll
        for (int kk = 0; kk < 16; kk++) {
            float a[8], bfr[8];
            *(float4*)(a)     = *(const float4*)&As[kk][ty * 8];
            *(float4*)(a + 4) = *(const float4*)&As[kk][ty * 8 + 4];
            *(float4*)(bfr)     = *(const float4*)&Bs[kk][tx * 8];
            *(float4*)(bfr + 4) = *(const float4*)&Bs[kk][tx * 8 + 4];
            #pragma unroll
            for (int i = 0; i < 8; i++)
                #pragma unroll
                for (int j = 0; j < 8; j++) acc[i][j] += a[i] * bfr[j];
        }
        __syncthreads();
    }
    float bqv[8];
    #pragma unroll
    for (int i = 0; i < 8; i++) bqv[i] = bq[m0 + ty * 8 + i];
    const bool use_w = (m0 < (Cch / 2));   // whole 128-wide m-tile is on one side of C/2
    #pragma unroll
    for (int j = 0; j < 8; j++) {
        int n = n0 + tx * 8 + j;
        float pe = 0.05f * (1.0f / 63.0f) * (float)(use_w ? (n & 63) : ((n >> 6) & 63));
        float* op = out + (size_t)n * Cch + m0 + ty * 8;
        float4 r0 = make_float4(acc[0][j] + bqv[0] + pe, acc[1][j] + bqv[1] + pe,
                                acc[2][j] + bqv[2] + pe, acc[3][j] + bqv[3] + pe);
        float4 r1 = make_float4(acc[4][j] + bqv[4] + pe, acc[5][j] + bqv[5] + pe,
                                acc[6][j] + bqv[6] + pe, acc[7][j] + bqv[7] + pe);
        *(float4*)op = r0; *(float4*)(op + 4) = r1;
    }
}

// =====================================================================
// In-place LayerNorm over rows of length 512. which: 1 -> g_q, 0 -> g_k.
// =====================================================================
__global__ __launch_bounds__(128) void ln512_kernel(
    int which, const float* __restrict__ g, const float* __restrict__ beta)
{
    float* data = which ? g_q : g_k;
    float* p = data + (size_t)blockIdx.x * Cch;
    int t = threadIdx.x;
    float4 v = *(float4*)(p + t * 4);
    float s = v.x + v.y + v.z + v.w;
    float q = v.x * v.x + v.y * v.y + v.z * v.z + v.w * v.w;
    #pragma unroll
    for (int o = 16; o > 0; o >>= 1) {
        s += __shfl_down_sync(0xffffffffu, s, o);
        q += __shfl_down_sync(0xffffffffu, q, o);
    }
    __shared__ float ws[4], wq2[4];
    __shared__ float mean_s, rstd_s;
    if ((t & 31) == 0) { ws[t >> 5] = s; wq2[t >> 5] = q; }
    __syncthreads();
    if (t == 0) {
        float S = ws[0] + ws[1] + ws[2] + ws[3];
        float Q = wq2[0] + wq2[1] + wq2[2] + wq2[3];
        float m = S * (1.0f / 512.0f);
        float var = Q * (1.0f / 512.0f) - m * m;
        mean_s = m;
        rstd_s = rsqrtf(var + 1e-5f);
    }
    __syncthreads();
    float m = mean_s, r = rstd_s;
    float4 g4 = *(const float4*)(g + t * 4);
    float4 b4 = *(const float4*)(beta + t * 4);
    v.x = (v.x - m) * r * g4.x + b4.x;
    v.y = (v.y - m) * r * g4.y + b4.y;
    v.z = (v.z - m) * r * g4.z + b4.z;
    v.w = (v.w - m) * r * g4.w + b4.w;
    *(float4*)(p + t * 4) = v;
}

// =====================================================================
// Attention: block = (64 query tokens, one head, one batch). grid (64, 8, 16).
// S = Q K^T * 0.125 -> softmax over 77 keys -> O = P V (1/sum folded in epilogue).
// Dynamic smem: Qs[64][65], Ks[80][65], Vs[80][64], Ps[80][65], inv[64]
// =====================================================================
#define ATTN_SMEM ((64 * 65 + 80 * 65 + 80 * 64 + 80 * 65 + 64) * 4)

__global__ __launch_bounds__(256) void attn_kernel()
{
    extern __shared__ float sm[];
    float* Qs = sm;                  // [64][65]
    float* Ks = Qs + 64 * 65;        // [80][65]  rows 77..79 zeroed
    float* Vs = Ks + 80 * 65;        // [80][64]
    float* Ps = Vs + 80 * 64;        // [80][65]  P^T: [l][t]
    float* inv = Ps + 80 * 65;       // [64]

    const int tid = threadIdx.x;
    const int t0 = blockIdx.x * 64, h = blockIdx.y, b = blockIdx.z;

    const float* qb = g_q + ((size_t)b * HWs + t0) * Cch + h * HDd;
    for (int f = tid; f < 64 * 16; f += 256) {
        int t = f >> 4, dc = (f & 15) << 2;
        float4 v = *(const float4*)(qb + (size_t)t * Cch + dc);
        float* d = Qs + t * 65 + dc;
        d[0] = v.x; d[1] = v.y; d[2] = v.z; d[3] = v.w;
    }
    const float* kb = g_k + (size_t)b * Lt * Cch + h * HDd;
    const float* vb = g_v + (size_t)b * Lt * Cch + h * HDd;
    for (int f = tid; f < 80 * 16; f += 256) {
        int l = f >> 4, dc = (f & 15) << 2;
        float4 k4 = make_float4(0.f, 0.f, 0.f, 0.f), v4 = make_float4(0.f, 0.f, 0.f, 0.f);
        if (l < Lt) {
            k4 = *(const float4*)(kb + (size_t)l * Cch + dc);
            v4 = *(const float4*)(vb + (size_t)l * Cch + dc);
        }
        float* kd = Ks + l * 65 + dc;
        kd[0] = k4.x; kd[1] = k4.y; kd[2] = k4.z; kd[3] = k4.w;
        *(float4*)(Vs + l * 64 + dc) = v4;
    }
    __syncthreads();

    const int tx = tid & 15, ty = tid >> 4;
    {
        float acc[4][5] = {};
        #pragma unroll 4
        for (int d = 0; d < HDd; d++) {
            float qv[4], kv[5];
            #pragma unroll
            for (int i = 0; i < 4; i++) qv[i] = Qs[(ty * 4 + i) * 65 + d];
            #pragma unroll
            for (int j = 0; j < 5; j++) kv[j] = Ks[(tx * 5 + j) * 65 + d];
            #pragma unroll
            for (int i = 0; i < 4; i++)
                #pragma unroll
                for (int j = 0; j < 5; j++) acc[i][j] += qv[i] * kv[j];
        }
        #pragma unroll
        for (int i = 0; i < 4; i++)
            #pragma unroll
            for (int j = 0; j < 5; j++)
                Ps[(tx * 5 + j) * 65 + ty * 4 + i] = acc[i][j] * 0.125f;
    }
    __syncthreads();

    if (tid < 64) {
        int t = tid;
        float mx = -1e30f;
        for (int l = 0; l < Lt; l++) mx = fmaxf(mx, Ps[l * 65 + t]);
        float s = 0.f;
        for (int l = 0; l < Lt; l++) {
            float e = __expf(Ps[l * 65 + t] - mx);
            Ps[l * 65 + t] = e;
            s += e;
        }
        inv[t] = 1.0f / s;
    }
    __syncthreads();

    float o[4][4] = {};
    for (int l = 0; l < Lt; l++) {
        float pv[4];
        #pragma unroll
        for (int i = 0; i < 4; i++) pv[i] = Ps[l * 65 + ty * 4 + i];
        float4 vv = *(const float4*)(Vs + l * 64 + tx * 4);
        #pragma unroll
        for (int i = 0; i < 4; i++) {
            o[i][0] += pv[i] * vv.x;
            o[i][1] += pv[i] * vv.y;
            o[i][2] += pv[i] * vv.z;
            o[i][3] += pv[i] * vv.w;
        }
    }
    float* ob = g_attn + ((size_t)b * HWs + t0) * Cch + h * HDd;
    #pragma unroll
    for (int i = 0; i < 4; i++) {
        float iv = inv[ty * 4 + i];
        float4 r = make_float4(o[i][0] * iv, o[i][1] * iv, o[i][2] * iv, o[i][3] * iv);
        *(float4*)(ob + (size_t)(ty * 4 + i) * Cch + tx * 4) = r;
    }
}

// =====================================================================
// Output projection (NT GEMM) + bias + residual, per batch:
// out[b][m=o][n=hw] = sum_c wo[m][c] * g_attn[b][n][c] + bo[m] + x[b][m][n]
// grid (32, 4, 16).
// =====================================================================
__global__ __launch_bounds__(256) void o_proj_kernel(
    const float* __restrict__ wo, const float* __restrict__ bo,
    const float* __restrict__ x, float* __restrict__ out)
{
    const int b = blockIdx.z;
    const float* Bm = g_attn + (size_t)b * HWs * Cch;
    __shared__ float As[16][132];
    __shared__ float Bs[16][132];
    const int m0 = blockIdx.y * 128, n0 = blockIdx.x * 128;
    const int tid = threadIdx.x;
    const int tx = tid & 15, ty = tid >> 4;
    float acc[8][8] = {};

    for (int k0 = 0; k0 < Cch; k0 += 16) {
        #pragma unroll
        for (int u = 0; u < 2; u++) {
            int f = tid + 256 * u;
            int r = f >> 2, kc = (f & 3) << 2;
            float4 a4 = *(const float4*)(wo + (size_t)(m0 + r) * Cch + k0 + kc);
            As[kc][r] = a4.x; As[kc + 1][r] = a4.y; As[kc + 2][r] = a4.z; As[kc + 3][r] = a4.w;
            float4 b4 = *(const float4*)(Bm + (size_t)(n0 + r) * Cch + k0 + kc);
            Bs[kc][r] = b4.x; Bs[kc + 1][r] = b4.y; Bs[kc + 2][r] = b4.z; Bs[kc + 3][r] = b4.w;
        }
        __syncthreads();
        #pragma unroll
        for (int kk = 0; kk < 16; kk++) {
            float a[8], bfr[8];
            *(float4*)(a)     = *(const float4*)&As[kk][ty * 8];
            *(float4*)(a + 4) = *(const float4*)&As[kk][ty * 8 + 4];
            *(float4*)(bfr)     = *(const float4*)&Bs[kk][tx * 8];
            *(float4*)(bfr + 4) = *(const float4*)&Bs[kk][tx * 8 + 4];
            #pragma unroll
            for (int i = 0; i < 8; i++)
                #pragma unroll
                for (int j = 0; j < 8; j++) acc[i][j] += a[i] * bfr[j];
        }
        __syncthreads();
    }
    #pragma unroll
    for (int i = 0; i < 8; i++) {
        int m = m0 + ty * 8 + i;
        size_t base = (size_t)b * Cch * HWs + (size_t)m * HWs + n0 + tx * 8;
        float bov = bo[m];
        float4 x0 = *(const float4*)(x + base);
        float4 x1 = *(const float4*)(x + base + 4);
        float4 r0 = make_float4(acc[i][0] + bov + x0.x, acc[i][1] + bov + x0.y,
                                acc[i][2] + bov + x0.z, acc[i][3] + bov + x0.w);
        float4 r1 = make_float4(acc[i][4] + bov + x1.x, acc[i][5] + bov + x1.y,
                                acc[i][6] + bov + x1.z, acc[i][7] + bov + x1.w);
        *(float4*)(out + base) = r0;
        *(float4*)(out + base + 4) = r1;
    }
}

// =====================================================================
extern "C" void kernel_launch(void* const* d_in, const int* in_sizes, int n_in,
                              void* d_out, int out_size)
{
    const float* x  = (const float*)d_in[0];
    const float* tf = (const float*)d_in[1];
    const float* wq = (const float*)d_in[2];
    const float* bq = (const float*)d_in[3];
    const float* wk = (const float*)d_in[4];
    const float* bk = (const float*)d_in[5];
    const float* wv = (const float*)d_in[6];
    const float* bv = (const float*)d_in[7];
    const float* wo = (const float*)d_in[8];
    const float* bo = (const float*)d_in[9];
    const float* g1 = (const float*)d_in[10];
    const float* b1 = (const float*)d_in[11];
    const float* g2 = (const float*)d_in[12];
    const float* b2 = (const float*)d_in[13];
    float* out = (float*)d_out;

    cudaFuncSetAttribute(attn_kernel, cudaFuncAttributeMaxDynamicSharedMemorySize, ATTN_SMEM);

    kv_proj_kernel<<<dim3(4, 10, 2), 256>>>(tf, wk, bk, wv, bv);
    ln512_kernel<<<Bsz * Lt, 128>>>(0, g2, b2);
    q_proj_kernel<<<dim3(32, 4, 16), 256>>>(x, wq, bq);
    ln512_kernel<<<Bsz * HWs, 128>>>(1, g1, b1);
    attn_kernel<<<dim3(64, 8, 16), 256, ATTN_SMEM>>>();
    o_proj_kernel<<<dim3(32, 4, 16), 256>>>(wo, bo, x, out);
}

// round 3
// speedup vs baseline: 2.3664x; 2.3664x over previous
#include <cuda_runtime.h>
#include <cstdint>

#define Bsz 16
#define Cch 512
#define HWs 4096
#define Lt  77
#define Dd  768
#define NHh 8
#define HDd 64

// ---------------- scratch (device globals; no allocation allowed) ----------------
__device__ float g_q[(size_t)Bsz * HWs * Cch];     // token-major [b][hw][c]; LN in place
__device__ float g_attn[(size_t)Bsz * HWs * Cch];  // attention output, token-major
__device__ float g_k[Bsz * Lt * Cch];              // token-major [b*l][c]; LN in place
__device__ float g_v[Bsz * Lt * Cch];

// =====================================================================
// tf32 mma.sync helpers
// =====================================================================
__device__ __forceinline__ uint32_t f2tf(float f) {
    uint32_t r;
    asm("cvt.rna.tf32.f32 %0, %1;" : "=r"(r) : "f"(f));
    return r;
}

__device__ __forceinline__ void mma8(float* c, const uint32_t* a, const uint32_t* b) {
    asm volatile(
        "mma.sync.aligned.m16n8k8.row.col.f32.tf32.tf32.f32 "
        "{%0,%1,%2,%3}, {%4,%5,%6,%7}, {%8,%9}, {%0,%1,%2,%3};"
        : "+f"(c[0]), "+f"(c[1]), "+f"(c[2]), "+f"(c[3])
        : "r"(a[0]), "r"(a[1]), "r"(a[2]), "r"(a[3]), "r"(b[0]), "r"(b[1]));
}

#define AS_STR 36
#define BS_STR 136

// Per-chunk compute: 4 k-steps of 8, warp tile 64m x 32n, 4x4 mma tiles.
__device__ __forceinline__ void compute_chunk(
    const uint32_t* __restrict__ As, const uint32_t* __restrict__ Bs,
    float cacc[4][4][4], int warp_m, int warp_n, int lane)
{
    const int g = lane >> 2, tg = lane & 3;
    #pragma unroll
    for (int ks = 0; ks < 4; ks++) {
        uint32_t af[4][4], bf[4][2];
        #pragma unroll
        for (int mt = 0; mt < 4; mt++) {
            int ar = warp_m * 64 + mt * 16 + g;
            int ac = ks * 8 + tg;
            af[mt][0] = As[ar * AS_STR + ac];
            af[mt][1] = As[(ar + 8) * AS_STR + ac];
            af[mt][2] = As[ar * AS_STR + ac + 4];
            af[mt][3] = As[(ar + 8) * AS_STR + ac + 4];
        }
        #pragma unroll
        for (int nt = 0; nt < 4; nt++) {
            int bn = warp_n * 32 + nt * 8 + g;
            int bk = ks * 8 + tg;
            bf[nt][0] = Bs[bk * BS_STR + bn];
            bf[nt][1] = Bs[(bk + 4) * BS_STR + bn];
        }
        #pragma unroll
        for (int mt = 0; mt < 4; mt++)
            #pragma unroll
            for (int nt = 0; nt < 4; nt++)
                mma8(cacc[mt][nt], af[mt], bf[nt]);
    }
}

// =====================================================================
// KV projection (NT): C[m=token][n=c] = sum_d tf[m][d] * W[n][d] + bias[n]
// M=1232, N=512, K=768. grid (4, 10, 2) z: 0->k, 1->v.
// =====================================================================
__global__ __launch_bounds__(256) void kv_proj_tc(
    const float* __restrict__ tf,
    const float* __restrict__ wk, const float* __restrict__ bk,
    const float* __restrict__ wv, const float* __restrict__ bv)
{
    const int M = Bsz * Lt;
    const float* W; const float* bias; float* out;
    if (blockIdx.z == 0) { W = wk; bias = bk; out = g_k; }
    else                 { W = wv; bias = bv; out = g_v; }

    __shared__ uint32_t As[128 * AS_STR];
    __shared__ uint32_t Bs[32 * BS_STR];

    const int m0 = blockIdx.y * 128, n0 = blockIdx.x * 128;
    const int tid = threadIdx.x, lane = tid & 31, wid = tid >> 5;
    const int warp_m = wid & 1, warp_n = wid >> 1;
    float cacc[4][4][4] = {};

    for (int k0 = 0; k0 < Dd; k0 += 32) {
        #pragma unroll
        for (int u = 0; u < 4; u++) {
            int f = tid + 256 * u;
            int r = f >> 3, c4 = (f & 7) << 2;
            // A: tf[m][k], row-major
            float4 a4 = make_float4(0.f, 0.f, 0.f, 0.f);
            if (m0 + r < M) a4 = *(const float4*)(tf + (size_t)(m0 + r) * Dd + k0 + c4);
            As[r * AS_STR + c4]     = f2tf(a4.x);
            As[r * AS_STR + c4 + 1] = f2tf(a4.y);
            As[r * AS_STR + c4 + 2] = f2tf(a4.z);
            As[r * AS_STR + c4 + 3] = f2tf(a4.w);
            // B: W[n][k] (NT) -> Bs[k][n]
            float4 w4 = *(const float4*)(W + (size_t)(n0 + r) * Dd + k0 + c4);
            Bs[(c4)     * BS_STR + r] = f2tf(w4.x);
            Bs[(c4 + 1) * BS_STR + r] = f2tf(w4.y);
            Bs[(c4 + 2) * BS_STR + r] = f2tf(w4.z);
            Bs[(c4 + 3) * BS_STR + r] = f2tf(w4.w);
        }
        __syncthreads();
        compute_chunk(As, Bs, cacc, warp_m, warp_n, lane);
        __syncthreads();
    }

    const int g = lane >> 2, tg = lane & 3;
    #pragma unroll
    for (int mt = 0; mt < 4; mt++) {
        #pragma unroll
        for (int nt = 0; nt < 4; nt++) {
            int m = m0 + warp_m * 64 + mt * 16 + g;
            int n = n0 + warp_n * 32 + nt * 8 + tg * 2;
            float2 bb = *(const float2*)(bias + n);
            if (m < M) {
                float2 r0 = make_float2(cacc[mt][nt][0] + bb.x, cacc[mt][nt][1] + bb.y);
                *(float2*)(out + (size_t)m * Cch + n) = r0;
            }
            if (m + 8 < M) {
                float2 r1 = make_float2(cacc[mt][nt][2] + bb.x, cacc[mt][nt][3] + bb.y);
                *(float2*)(out + (size_t)(m + 8) * Cch + n) = r1;
            }
        }
    }
}

// =====================================================================
// Q projection, token-major output:
// C[m=token][n=chan] = sum_c X[c][m] * wq[n][c] + bq[n] + 0.05*pe(n,m)
// M=4096, N=512, K=512. grid (4, 32, 16).
// =====================================================================
__global__ __launch_bounds__(256) void q_proj_tc(
    const float* __restrict__ x, const float* __restrict__ wq, const float* __restrict__ bq)
{
    const int b = blockIdx.z;
    const float* X = x + (size_t)b * Cch * HWs;
    float* out = g_q + (size_t)b * HWs * Cch;

    __shared__ uint32_t As[128 * AS_STR];
    __shared__ uint32_t Bs[32 * BS_STR];

    const int m0 = blockIdx.y * 128, n0 = blockIdx.x * 128;
    const int tid = threadIdx.x, lane = tid & 31, wid = tid >> 5;
    const int warp_m = wid & 1, warp_n = wid >> 1;
    float cacc[4][4][4] = {};

    for (int k0 = 0; k0 < Cch; k0 += 32) {
        #pragma unroll
        for (int u = 0; u < 4; u++) {
            int f = tid + 256 * u;
            // A: X[k][m] strided (m contiguous) -> As[m][k]
            int kk = f >> 5, mc4 = (f & 31) << 2;
            float4 a4 = *(const float4*)(X + (size_t)(k0 + kk) * HWs + m0 + mc4);
            As[(mc4)     * AS_STR + kk] = f2tf(a4.x);
            As[(mc4 + 1) * AS_STR + kk] = f2tf(a4.y);
            As[(mc4 + 2) * AS_STR + kk] = f2tf(a4.z);
            As[(mc4 + 3) * AS_STR + kk] = f2tf(a4.w);
            // B: wq[n][k] (NT) -> Bs[k][n]
            int r = f >> 3, c4 = (f & 7) << 2;
            float4 w4 = *(const float4*)(wq + (size_t)(n0 + r) * Cch + k0 + c4);
            Bs[(c4)     * BS_STR + r] = f2tf(w4.x);
            Bs[(c4 + 1) * BS_STR + r] = f2tf(w4.y);
            Bs[(c4 + 2) * BS_STR + r] = f2tf(w4.z);
            Bs[(c4 + 3) * BS_STR + r] = f2tf(w4.w);
        }
        __syncthreads();
        compute_chunk(As, Bs, cacc, warp_m, warp_n, lane);
        __syncthreads();
    }

    const int g = lane >> 2, tg = lane & 3;
    const float pes = 0.05f / 63.0f;
    #pragma unroll
    for (int mt = 0; mt < 4; mt++) {
        #pragma unroll
        for (int nt = 0; nt < 4; nt++) {
            int m = m0 + warp_m * 64 + mt * 16 + g;    // token
            int n = n0 + warp_n * 32 + nt * 8 + tg * 2; // channel
            float2 bb = *(const float2*)(bq + n);
            bool use_x = n < (Cch / 2);
            float pe0 = pes * (float)(use_x ? (m & 63) : ((m >> 6) & 63));
            float pe1 = pes * (float)(use_x ? ((m + 8) & 63) : (((m + 8) >> 6) & 63));
            float2 r0 = make_float2(cacc[mt][nt][0] + bb.x + pe0, cacc[mt][nt][1] + bb.y + pe0);
            float2 r1 = make_float2(cacc[mt][nt][2] + bb.x + pe1, cacc[mt][nt][3] + bb.y + pe1);
            *(float2*)(out + (size_t)m * Cch + n) = r0;
            *(float2*)(out + (size_t)(m + 8) * Cch + n) = r1;
        }
    }
}

// =====================================================================
// Output projection + bias + residual:
// C[m=chan][n=token] = sum_c wo[m][c] * g_attn[n][c] + bo[m] + x[b][m][n]
// M=512, N=4096, K=512. grid (32, 4, 16).
// =====================================================================
__global__ __launch_bounds__(256) void o_proj_tc(
    const float* __restrict__ wo, const float* __restrict__ bo,
    const float* __restrict__ x, float* __restrict__ outp)
{
    const int b = blockIdx.z;
    const float* Bm = g_attn + (size_t)b * HWs * Cch;

    __shared__ uint32_t As[128 * AS_STR];
    __shared__ uint32_t Bs[32 * BS_STR];

    const int m0 = blockIdx.y * 128, n0 = blockIdx.x * 128;
    const int tid = threadIdx.x, lane = tid & 31, wid = tid >> 5;
    const int warp_m = wid & 1, warp_n = wid >> 1;
    float cacc[4][4][4] = {};

    for (int k0 = 0; k0 < Cch; k0 += 32) {
        #pragma unroll
        for (int u = 0; u < 4; u++) {
            int f = tid + 256 * u;
            int r = f >> 3, c4 = (f & 7) << 2;
            // A: wo[m][k], row-major
            float4 a4 = *(const float4*)(wo + (size_t)(m0 + r) * Cch + k0 + c4);
            As[r * AS_STR + c4]     = f2tf(a4.x);
            As[r * AS_STR + c4 + 1] = f2tf(a4.y);
            As[r * AS_STR + c4 + 2] = f2tf(a4.z);
            As[r * AS_STR + c4 + 3] = f2tf(a4.w);
            // B: g_attn[n][k] (NT) -> Bs[k][n]
            float4 b4 = *(const float4*)(Bm + (size_t)(n0 + r) * Cch + k0 + c4);
            Bs[(c4)     * BS_STR + r] = f2tf(b4.x);
            Bs[(c4 + 1) * BS_STR + r] = f2tf(b4.y);
            Bs[(c4 + 2) * BS_STR + r] = f2tf(b4.z);
            Bs[(c4 + 3) * BS_STR + r] = f2tf(b4.w);
        }
        __syncthreads();
        compute_chunk(As, Bs, cacc, warp_m, warp_n, lane);
        __syncthreads();
    }

    const int g = lane >> 2, tg = lane & 3;
    #pragma unroll
    for (int mt = 0; mt < 4; mt++) {
        #pragma unroll
        for (int nt = 0; nt < 4; nt++) {
            int m = m0 + warp_m * 64 + mt * 16 + g;     // channel
            int n = n0 + warp_n * 32 + nt * 8 + tg * 2; // token
            float bo0 = bo[m], bo1 = bo[m + 8];
            size_t i0 = (size_t)b * Cch * HWs + (size_t)m * HWs + n;
            size_t i1 = (size_t)b * Cch * HWs + (size_t)(m + 8) * HWs + n;
            float2 x0 = *(const float2*)(x + i0);
            float2 x1 = *(const float2*)(x + i1);
            float2 r0 = make_float2(cacc[mt][nt][0] + bo0 + x0.x, cacc[mt][nt][1] + bo0 + x0.y);
            float2 r1 = make_float2(cacc[mt][nt][2] + bo1 + x1.x, cacc[mt][nt][3] + bo1 + x1.y);
            *(float2*)(outp + i0) = r0;
            *(float2*)(outp + i1) = r1;
        }
    }
}

// =====================================================================
// In-place LayerNorm over rows of length 512. which: 1 -> g_q, 0 -> g_k.
// =====================================================================
__global__ __launch_bounds__(128) void ln512_kernel(
    int which, const float* __restrict__ g, const float* __restrict__ beta)
{
    float* data = which ? g_q : g_k;
    float* p = data + (size_t)blockIdx.x * Cch;
    int t = threadIdx.x;
    float4 v = *(float4*)(p + t * 4);
    float s = v.x + v.y + v.z + v.w;
    float q = v.x * v.x + v.y * v.y + v.z * v.z + v.w * v.w;
    #pragma unroll
    for (int o = 16; o > 0; o >>= 1) {
        s += __shfl_down_sync(0xffffffffu, s, o);
        q += __shfl_down_sync(0xffffffffu, q, o);
    }
    __shared__ float ws[4], wq2[4];
    __shared__ float mean_s, rstd_s;
    if ((t & 31) == 0) { ws[t >> 5] = s; wq2[t >> 5] = q; }
    __syncthreads();
    if (t == 0) {
        float S = ws[0] + ws[1] + ws[2] + ws[3];
        float Q = wq2[0] + wq2[1] + wq2[2] + wq2[3];
        float m = S * (1.0f / 512.0f);
        float var = Q * (1.0f / 512.0f) - m * m;
        mean_s = m;
        rstd_s = rsqrtf(var + 1e-5f);
    }
    __syncthreads();
    float m = mean_s, r = rstd_s;
    float4 g4 = *(const float4*)(g + t * 4);
    float4 b4 = *(const float4*)(beta + t * 4);
    v.x = (v.x - m) * r * g4.x + b4.x;
    v.y = (v.y - m) * r * g4.y + b4.y;
    v.z = (v.z - m) * r * g4.z + b4.z;
    v.w = (v.w - m) * r * g4.w + b4.w;
    *(float4*)(p + t * 4) = v;
}

// =====================================================================
// Attention: block = (64 query tokens, one head, one batch). grid (64, 8, 16).
// =====================================================================
#define ATTN_SMEM ((64 * 65 + 80 * 65 + 80 * 64 + 80 * 65 + 64) * 4)

__global__ __launch_bounds__(256) void attn_kernel()
{
    extern __shared__ float sm[];
    float* Qs = sm;                  // [64][65]
    float* Ks = Qs + 64 * 65;        // [80][65]  rows 77..79 zeroed
    float* Vs = Ks + 80 * 65;        // [80][64]
    float* Ps = Vs + 80 * 64;        // [80][65]  P^T: [l][t]
    float* inv = Ps + 80 * 65;       // [64]

    const int tid = threadIdx.x;
    const int t0 = blockIdx.x * 64, h = blockIdx.y, b = blockIdx.z;

    const float* qb = g_q + ((size_t)b * HWs + t0) * Cch + h * HDd;
    for (int f = tid; f < 64 * 16; f += 256) {
        int t = f >> 4, dc = (f & 15) << 2;
        float4 v = *(const float4*)(qb + (size_t)t * Cch + dc);
        float* d = Qs + t * 65 + dc;
        d[0] = v.x; d[1] = v.y; d[2] = v.z; d[3] = v.w;
    }
    const float* kb = g_k + (size_t)b * Lt * Cch + h * HDd;
    const float* vb = g_v + (size_t)b * Lt * Cch + h * HDd;
    for (int f = tid; f < 80 * 16; f += 256) {
        int l = f >> 4, dc = (f & 15) << 2;
        float4 k4 = make_float4(0.f, 0.f, 0.f, 0.f), v4 = make_float4(0.f, 0.f, 0.f, 0.f);
        if (l < Lt) {
            k4 = *(const float4*)(kb + (size_t)l * Cch + dc);
            v4 = *(const float4*)(vb + (size_t)l * Cch + dc);
        }
        float* kd = Ks + l * 65 + dc;
        kd[0] = k4.x; kd[1] = k4.y; kd[2] = k4.z; kd[3] = k4.w;
        *(float4*)(Vs + l * 64 + dc) = v4;
    }
    __syncthreads();

    const int tx = tid & 15, ty = tid >> 4;
    {
        float acc[4][5] = {};
        #pragma unroll 4
        for (int d = 0; d < HDd; d++) {
            float qv[4], kv[5];
            #pragma unroll
            for (int i = 0; i < 4; i++) qv[i] = Qs[(ty * 4 + i) * 65 + d];
            #pragma unroll
            for (int j = 0; j < 5; j++) kv[j] = Ks[(tx * 5 + j) * 65 + d];
            #pragma unroll
            for (int i = 0; i < 4; i++)
                #pragma unroll
                for (int j = 0; j < 5; j++) acc[i][j] += qv[i] * kv[j];
        }
        #pragma unroll
        for (int i = 0; i < 4; i++)
            #pragma unroll
            for (int j = 0; j < 5; j++)
                Ps[(tx * 5 + j) * 65 + ty * 4 + i] = acc[i][j] * 0.125f;
    }
    __syncthreads();

    if (tid < 64) {
        int t = tid;
        float mx = -1e30f;
        for (int l = 0; l < Lt; l++) mx = fmaxf(mx, Ps[l * 65 + t]);
        float s = 0.f;
        for (int l = 0; l < Lt; l++) {
            float e = __expf(Ps[l * 65 + t] - mx);
            Ps[l * 65 + t] = e;
            s += e;
        }
        inv[t] = 1.0f / s;
    }
    __syncthreads();

    float o[4][4] = {};
    for (int l = 0; l < Lt; l++) {
        float pv[4];
        #pragma unroll
        for (int i = 0; i < 4; i++) pv[i] = Ps[l * 65 + ty * 4 + i];
        float4 vv = *(const float4*)(Vs + l * 64 + tx * 4);
        #pragma unroll
        for (int i = 0; i < 4; i++) {
            o[i][0] += pv[i] * vv.x;
            o[i][1] += pv[i] * vv.y;
            o[i][2] += pv[i] * vv.z;
            o[i][3] += pv[i] * vv.w;
        }
    }
    float* ob = g_attn + ((size_t)b * HWs + t0) * Cch + h * HDd;
    #pragma unroll
    for (int i = 0; i < 4; i++) {
        float iv = inv[ty * 4 + i];
        float4 r = make_float4(o[i][0] * iv, o[i][1] * iv, o[i][2] * iv, o[i][3] * iv);
        *(float4*)(ob + (size_t)(ty * 4 + i) * Cch + tx * 4) = r;
    }
}

// =====================================================================
extern "C" void kernel_launch(void* const* d_in, const int* in_sizes, int n_in,
                              void* d_out, int out_size)
{
    const float* x  = (const float*)d_in[0];
    const float* tf = (const float*)d_in[1];
    const float* wq = (const float*)d_in[2];
    const float* bq = (const float*)d_in[3];
    const float* wk = (const float*)d_in[4];
    const float* bk = (const float*)d_in[5];
    const float* wv = (const float*)d_in[6];
    const float* bv = (const float*)d_in[7];
    const float* wo = (const float*)d_in[8];
    const float* bo = (const float*)d_in[9];
    const float* g1 = (const float*)d_in[10];
    const float* b1 = (const float*)d_in[11];
    const float* g2 = (const float*)d_in[12];
    const float* b2 = (const float*)d_in[13];
    float* out = (float*)d_out;

    cudaFuncSetAttribute(attn_kernel, cudaFuncAttributeMaxDynamicSharedMemorySize, ATTN_SMEM);

    kv_proj_tc<<<dim3(4, 10, 2), 256>>>(tf, wk, bk, wv, bv);
    ln512_kernel<<<Bsz * Lt, 128>>>(0, g2, b2);
    q_proj_tc<<<dim3(4, 32, 16), 256>>>(x, wq, bq);
    ln512_kernel<<<Bsz * HWs, 128>>>(1, g1, b1);
    attn_kernel<<<dim3(64, 8, 16), 256, ATTN_SMEM>>>();
    o_proj_tc<<<dim3(32, 4, 16), 256>>>(wo, bo, x, out);
}

// round 4
// speedup vs baseline: 3.4519x; 1.4587x over previous
#include <cuda_runtime.h>
#include <cstdint>

#define Bsz 16
#define Cch 512
#define HWs 4096
#define Lt  77
#define Dd  768
#define NHh 8
#define HDd 64

// ---------------- scratch (device globals; no allocation allowed) ----------------
__device__ float g_q[(size_t)Bsz * HWs * Cch];     // token-major [b][hw][c] (pre-LN)
__device__ float g_attn[(size_t)Bsz * HWs * Cch];  // attention output, token-major
__device__ float g_k[Bsz * Lt * Cch];              // token-major [b*l][c]; LN in place
__device__ float g_v[Bsz * Lt * Cch];
__device__ float g_mu[Bsz * HWs];                  // q LN stats
__device__ float g_rs[Bsz * HWs];

// =====================================================================
// helpers
// =====================================================================
__device__ __forceinline__ void mma8(float* c, const uint32_t* a, const uint32_t* b) {
    asm volatile(
        "mma.sync.aligned.m16n8k8.row.col.f32.tf32.tf32.f32 "
        "{%0,%1,%2,%3}, {%4,%5,%6,%7}, {%8,%9}, {%0,%1,%2,%3};"
        : "+f"(c[0]), "+f"(c[1]), "+f"(c[2]), "+f"(c[3])
        : "r"(a[0]), "r"(a[1]), "r"(a[2]), "r"(a[3]), "r"(b[0]), "r"(b[1]));
}

__device__ __forceinline__ void cp16(uint32_t dst, const void* src) {
    asm volatile("cp.async.cg.shared.global [%0], [%1], 16;" :: "r"(dst), "l"(src));
}
__device__ __forceinline__ void cp16z(uint32_t dst, const void* src, bool pred) {
    int sz = pred ? 16 : 0;
    asm volatile("cp.async.cg.shared.global [%0], [%1], 16, %2;" :: "r"(dst), "l"(src), "r"(sz));
}
__device__ __forceinline__ void cp_commit() { asm volatile("cp.async.commit_group;"); }
__device__ __forceinline__ void cp_wait1() { asm volatile("cp.async.wait_group 1;"); }
__device__ __forceinline__ void cp_wait0() { asm volatile("cp.async.wait_group 0;"); }

#define AS_STR 36      // A smem [128][36] row-major m x k   (banks 4g+tg: conflict-free)
#define BS_STR 36      // B smem [128][36] row-major n x k   (banks 4g+tg: conflict-free)
#define AQ_STR 136     // q_proj A smem [32][136] k x m      (banks 8tg+g: conflict-free)
#define STAGE_A (128 * AS_STR)
#define STAGE_B (128 * BS_STR)
#define STAGE_AQ (32 * AQ_STR)

// compute one k=32 chunk; A row-major [m][k] str 36, B row-major [n][k] str 36
__device__ __forceinline__ void mma_chunk(
    const uint32_t* __restrict__ As, const uint32_t* __restrict__ Bs,
    float cacc[4][4][4], int wm, int wn, int g, int tg)
{
    #pragma unroll
    for (int ks = 0; ks < 4; ks++) {
        uint32_t af[4][4], bf[4][2];
        #pragma unroll
        for (int mt = 0; mt < 4; mt++) {
            int base = (wm * 64 + mt * 16 + g) * AS_STR + ks * 8 + tg;
            af[mt][0] = As[base];
            af[mt][1] = As[base + 8 * AS_STR];
            af[mt][2] = As[base + 4];
            af[mt][3] = As[base + 8 * AS_STR + 4];
        }
        #pragma unroll
        for (int nt = 0; nt < 4; nt++) {
            int bb = (wn * 32 + nt * 8 + g) * BS_STR + ks * 8 + tg;
            bf[nt][0] = Bs[bb];
            bf[nt][1] = Bs[bb + 4];
        }
        #pragma unroll
        for (int mt = 0; mt < 4; mt++)
            #pragma unroll
            for (int nt = 0; nt < 4; nt++)
                mma8(cacc[mt][nt], af[mt], bf[nt]);
    }
}

// compute one k=32 chunk; A k-major [k][m] str 136, B row-major [n][k] str 36
__device__ __forceinline__ void mma_chunk_kmaj(
    const uint32_t* __restrict__ As, const uint32_t* __restrict__ Bs,
    float cacc[4][4][4], int wm, int wn, int g, int tg)
{
    #pragma unroll
    for (int ks = 0; ks < 4; ks++) {
        uint32_t af[4][4], bf[4][2];
        #pragma unroll
        for (int mt = 0; mt < 4; mt++) {
            int m = wm * 64 + mt * 16 + g;
            af[mt][0] = As[(ks * 8 + tg) * AQ_STR + m];
            af[mt][1] = As[(ks * 8 + tg) * AQ_STR + m + 8];
            af[mt][2] = As[(ks * 8 + tg + 4) * AQ_STR + m];
            af[mt][3] = As[(ks * 8 + tg + 4) * AQ_STR + m + 8];
        }
        #pragma unroll
        for (int nt = 0; nt < 4; nt++) {
            int bb = (wn * 32 + nt * 8 + g) * BS_STR + ks * 8 + tg;
            bf[nt][0] = Bs[bb];
            bf[nt][1] = Bs[bb + 4];
        }
        #pragma unroll
        for (int mt = 0; mt < 4; mt++)
            #pragma unroll
            for (int nt = 0; nt < 4; nt++)
                mma8(cacc[mt][nt], af[mt], bf[nt]);
    }
}

// =====================================================================
// KV projection (NT): C[m=token][n=c] = sum_d tf[m][d] * W[n][d] + bias[n]
// M=1232, N=512, K=768. grid (4, 10, 2) z: 0->k, 1->v.
// =====================================================================
__global__ __launch_bounds__(256, 2) void kv_proj_tc(
    const float* __restrict__ tf,
    const float* __restrict__ wk, const float* __restrict__ bk,
    const float* __restrict__ wv, const float* __restrict__ bv)
{
    const int M = Bsz * Lt;
    const float* W; const float* bias; float* out;
    if (blockIdx.z == 0) { W = wk; bias = bk; out = g_k; }
    else                 { W = wv; bias = bv; out = g_v; }

    extern __shared__ uint32_t dsm[];
    uint32_t* Asm[2] = { dsm, dsm + STAGE_A };
    uint32_t* Bsm[2] = { dsm + 2 * STAGE_A, dsm + 2 * STAGE_A + STAGE_B };

    const int m0 = blockIdx.y * 128, n0 = blockIdx.x * 128;
    const int tid = threadIdx.x, lane = tid & 31, wid = tid >> 5;
    const int wm = wid & 1, wn = wid >> 1;
    const int g = lane >> 2, tg = lane & 3;
    const int r = tid >> 3, c4 = (tid & 7) << 2;       // 32 rows covered per 256 thr pass
    float cacc[4][4][4] = {};

    auto load_stage = [&](int st, int k0) {
        #pragma unroll
        for (int u = 0; u < 4; u++) {
            int rr = r + u * 32;
            uint32_t da = __cvta_generic_to_shared(&Asm[st][rr * AS_STR + c4]);
            cp16z(da, tf + (size_t)(m0 + rr) * Dd + k0 + c4, (m0 + rr) < M);
            uint32_t db = __cvta_generic_to_shared(&Bsm[st][rr * BS_STR + c4]);
            cp16(db, W + (size_t)(n0 + rr) * Dd + k0 + c4);
        }
        cp_commit();
    };

    load_stage(0, 0);
    const int NCH = Dd / 32;
    for (int ch = 0; ch < NCH; ch++) {
        int st = ch & 1;
        if (ch + 1 < NCH) { load_stage(st ^ 1, (ch + 1) * 32); cp_wait1(); }
        else cp_wait0();
        __syncthreads();
        mma_chunk(Asm[st], Bsm[st], cacc, wm, wn, g, tg);
        __syncthreads();
    }

    #pragma unroll
    for (int mt = 0; mt < 4; mt++) {
        #pragma unroll
        for (int nt = 0; nt < 4; nt++) {
            int m = m0 + wm * 64 + mt * 16 + g;
            int n = n0 + wn * 32 + nt * 8 + tg * 2;
            float2 bb = *(const float2*)(bias + n);
            if (m < M) {
                float2 r0 = make_float2(cacc[mt][nt][0] + bb.x, cacc[mt][nt][1] + bb.y);
                *(float2*)(out + (size_t)m * Cch + n) = r0;
            }
            if (m + 8 < M) {
                float2 r1 = make_float2(cacc[mt][nt][2] + bb.x, cacc[mt][nt][3] + bb.y);
                *(float2*)(out + (size_t)(m + 8) * Cch + n) = r1;
            }
        }
    }
}

// =====================================================================
// Q projection, token-major output:
// C[m=token][n=chan] = sum_c X[c][m] * wq[n][c] + bq[n] + 0.05*pe(n,m)
// M=4096, N=512, K=512. grid (4, 32, 16).
// =====================================================================
__global__ __launch_bounds__(256, 2) void q_proj_tc(
    const float* __restrict__ x, const float* __restrict__ wq, const float* __restrict__ bq)
{
    const int b = blockIdx.z;
    const float* X = x + (size_t)b * Cch * HWs;
    float* out = g_q + (size_t)b * HWs * Cch;

    extern __shared__ uint32_t dsm[];
    uint32_t* Asm[2] = { dsm, dsm + STAGE_AQ };
    uint32_t* Bsm[2] = { dsm + 2 * STAGE_AQ, dsm + 2 * STAGE_AQ + STAGE_B };

    const int m0 = blockIdx.y * 128, n0 = blockIdx.x * 128;
    const int tid = threadIdx.x, lane = tid & 31, wid = tid >> 5;
    const int wm = wid & 1, wn = wid >> 1;
    const int g = lane >> 2, tg = lane & 3;
    const int kk = tid >> 5, mc4 = (tid & 31) << 2;    // A loader: 8 k-rows per pass
    const int r = tid >> 3, c4 = (tid & 7) << 2;       // B loader
    float cacc[4][4][4] = {};

    auto load_stage = [&](int st, int k0) {
        #pragma unroll
        for (int u = 0; u < 4; u++) {
            int kr = kk + u * 8;
            uint32_t da = __cvta_generic_to_shared(&Asm[st][kr * AQ_STR + mc4]);
            cp16(da, X + (size_t)(k0 + kr) * HWs + m0 + mc4);
            int rr = r + u * 32;
            uint32_t db = __cvta_generic_to_shared(&Bsm[st][rr * BS_STR + c4]);
            cp16(db, wq + (size_t)(n0 + rr) * Cch + k0 + c4);
        }
        cp_commit();
    };

    load_stage(0, 0);
    const int NCH = Cch / 32;
    for (int ch = 0; ch < NCH; ch++) {
        int st = ch & 1;
        if (ch + 1 < NCH) { load_stage(st ^ 1, (ch + 1) * 32); cp_wait1(); }
        else cp_wait0();
        __syncthreads();
        mma_chunk_kmaj(Asm[st], Bsm[st], cacc, wm, wn, g, tg);
        __syncthreads();
    }

    const float pes = 0.05f / 63.0f;
    #pragma unroll
    for (int mt = 0; mt < 4; mt++) {
        #pragma unroll
        for (int nt = 0; nt < 4; nt++) {
            int m = m0 + wm * 64 + mt * 16 + g;     // token
            int n = n0 + wn * 32 + nt * 8 + tg * 2; // channel
            float2 bb = *(const float2*)(bq + n);
            bool use_x = n < (Cch / 2);
            float pe0 = pes * (float)(use_x ? (m & 63) : ((m >> 6) & 63));
            float pe1 = pes * (float)(use_x ? ((m + 8) & 63) : (((m + 8) >> 6) & 63));
            float2 r0 = make_float2(cacc[mt][nt][0] + bb.x + pe0, cacc[mt][nt][1] + bb.y + pe0);
            float2 r1 = make_float2(cacc[mt][nt][2] + bb.x + pe1, cacc[mt][nt][3] + bb.y + pe1);
            *(float2*)(out + (size_t)m * Cch + n) = r0;
            *(float2*)(out + (size_t)(m + 8) * Cch + n) = r1;
        }
    }
}

// =====================================================================
// Output projection + bias + residual:
// C[m=chan][n=token] = sum_c wo[m][c] * g_attn[n][c] + bo[m] + x[b][m][n]
// M=512, N=4096, K=512. grid (32, 4, 16).
// =====================================================================
__global__ __launch_bounds__(256, 2) void o_proj_tc(
    const float* __restrict__ wo, const float* __restrict__ bo,
    const float* __restrict__ x, float* __restrict__ outp)
{
    const int b = blockIdx.z;
    const float* Bm = g_attn + (size_t)b * HWs * Cch;

    extern __shared__ uint32_t dsm[];
    uint32_t* Asm[2] = { dsm, dsm + STAGE_A };
    uint32_t* Bsm[2] = { dsm + 2 * STAGE_A, dsm + 2 * STAGE_A + STAGE_B };

    const int m0 = blockIdx.y * 128, n0 = blockIdx.x * 128;
    const int tid = threadIdx.x, lane = tid & 31, wid = tid >> 5;
    const int wm = wid & 1, wn = wid >> 1;
    const int g = lane >> 2, tg = lane & 3;
    const int r = tid >> 3, c4 = (tid & 7) << 2;
    float cacc[4][4][4] = {};

    auto load_stage = [&](int st, int k0) {
        #pragma unroll
        for (int u = 0; u < 4; u++) {
            int rr = r + u * 32;
            uint32_t da = __cvta_generic_to_shared(&Asm[st][rr * AS_STR + c4]);
            cp16(da, wo + (size_t)(m0 + rr) * Cch + k0 + c4);
            uint32_t db = __cvta_generic_to_shared(&Bsm[st][rr * BS_STR + c4]);
            cp16(db, Bm + (size_t)(n0 + rr) * Cch + k0 + c4);
        }
        cp_commit();
    };

    load_stage(0, 0);
    const int NCH = Cch / 32;
    for (int ch = 0; ch < NCH; ch++) {
        int st = ch & 1;
        if (ch + 1 < NCH) { load_stage(st ^ 1, (ch + 1) * 32); cp_wait1(); }
        else cp_wait0();
        __syncthreads();
        mma_chunk(Asm[st], Bsm[st], cacc, wm, wn, g, tg);
        __syncthreads();
    }

    #pragma unroll
    for (int mt = 0; mt < 4; mt++) {
        #pragma unroll
        for (int nt = 0; nt < 4; nt++) {
            int m = m0 + wm * 64 + mt * 16 + g;     // channel
            int n = n0 + wn * 32 + nt * 8 + tg * 2; // token
            float bo0 = bo[m], bo1 = bo[m + 8];
            size_t i0 = (size_t)b * Cch * HWs + (size_t)m * HWs + n;
            size_t i1 = (size_t)b * Cch * HWs + (size_t)(m + 8) * HWs + n;
            float2 x0 = *(const float2*)(x + i0);
            float2 x1 = *(const float2*)(x + i1);
            float2 r0 = make_float2(cacc[mt][nt][0] + bo0 + x0.x, cacc[mt][nt][1] + bo0 + x0.y);
            float2 r1 = make_float2(cacc[mt][nt][2] + bo1 + x1.x, cacc[mt][nt][3] + bo1 + x1.y);
            *(float2*)(outp + i0) = r0;
            *(float2*)(outp + i1) = r1;
        }
    }
}

// =====================================================================
// In-place LayerNorm over rows of length 512 (for K only).
// =====================================================================
__global__ __launch_bounds__(128) void ln512_kernel(
    const float* __restrict__ g, const float* __restrict__ beta)
{
    float* p = g_k + (size_t)blockIdx.x * Cch;
    int t = threadIdx.x;
    float4 v = *(float4*)(p + t * 4);
    float s = v.x + v.y + v.z + v.w;
    float q = v.x * v.x + v.y * v.y + v.z * v.z + v.w * v.w;
    #pragma unroll
    for (int o = 16; o > 0; o >>= 1) {
        s += __shfl_down_sync(0xffffffffu, s, o);
        q += __shfl_down_sync(0xffffffffu, q, o);
    }
    __shared__ float ws[4], wq2[4];
    __shared__ float mean_s, rstd_s;
    if ((t & 31) == 0) { ws[t >> 5] = s; wq2[t >> 5] = q; }
    __syncthreads();
    if (t == 0) {
        float S = ws[0] + ws[1] + ws[2] + ws[3];
        float Q = wq2[0] + wq2[1] + wq2[2] + wq2[3];
        float m = S * (1.0f / 512.0f);
        float var = Q * (1.0f / 512.0f) - m * m;
        mean_s = m;
        rstd_s = rsqrtf(var + 1e-5f);
    }
    __syncthreads();
    float m = mean_s, rr = rstd_s;
    float4 g4 = *(const float4*)(g + t * 4);
    float4 b4 = *(const float4*)(beta + t * 4);
    v.x = (v.x - m) * rr * g4.x + b4.x;
    v.y = (v.y - m) * rr * g4.y + b4.y;
    v.z = (v.z - m) * rr * g4.z + b4.z;
    v.w = (v.w - m) * rr * g4.w + b4.w;
    *(float4*)(p + t * 4) = v;
}

// =====================================================================
// q LN stats: one warp per row of g_q, write mean / rstd.
// =====================================================================
__global__ __launch_bounds__(256) void ln_stats_kernel()
{
    int row = blockIdx.x * 8 + (threadIdx.x >> 5);
    int lane = threadIdx.x & 31;
    const float4* p = (const float4*)(g_q + (size_t)row * Cch);
    float s = 0.f, q = 0.f;
    #pragma unroll
    for (int i = 0; i < 4; i++) {
        float4 v = p[lane + i * 32];
        s += v.x + v.y + v.z + v.w;
        q += v.x * v.x + v.y * v.y + v.z * v.z + v.w * v.w;
    }
    #pragma unroll
    for (int o = 16; o > 0; o >>= 1) {
        s += __shfl_down_sync(0xffffffffu, s, o);
        q += __shfl_down_sync(0xffffffffu, q, o);
    }
    if (lane == 0) {
        float m = s * (1.0f / 512.0f);
        float var = q * (1.0f / 512.0f) - m * m;
        g_mu[row] = m;
        g_rs[row] = rsqrtf(var + 1e-5f);
    }
}

// =====================================================================
// Tensor-core attention with fused q-LN. block = 64 q tokens x head x batch.
// grid (64, 8, 16), 128 threads (4 warps, 16 q rows each).
// =====================================================================
#define QS_STR 68
#define KS_STR 68
#define VS_STR 68
#define PS_STR 84
#define ATTN_SMEM ((64 * QS_STR + 80 * KS_STR + 80 * VS_STR + 64 * PS_STR + 128) * 4)

__global__ __launch_bounds__(128) void attn_tc(
    const float* __restrict__ g1, const float* __restrict__ b1)
{
    extern __shared__ float sm[];
    float* Qs = sm;                       // [64][68]
    float* Ks = Qs + 64 * QS_STR;         // [80][68] rows 77..79 zero
    float* Vs = Ks + 80 * KS_STR;         // [80][68] rows 77..79 zero
    float* Ps = Vs + 80 * VS_STR;         // [64][84]
    float* mu_s = Ps + 64 * PS_STR;       // [64]
    float* rs_s = mu_s + 64;              // [64]

    const int tid = threadIdx.x, lane = tid & 31, w = tid >> 5;
    const int g = lane >> 2, tg = lane & 3;
    const int t0 = blockIdx.x * 64, h = blockIdx.y, b = blockIdx.z;

    if (tid < 64) {
        mu_s[tid] = g_mu[(size_t)b * HWs + t0 + tid];
        rs_s[tid] = g_rs[(size_t)b * HWs + t0 + tid];
    }
    __syncthreads();

    // load Q (with LN applied), K, V
    const float* qb = g_q + ((size_t)b * HWs + t0) * Cch + h * HDd;
    for (int f = tid; f < 64 * 16; f += 128) {
        int t = f >> 4, dc = (f & 15) << 2;
        float4 v = *(const float4*)(qb + (size_t)t * Cch + dc);
        float4 gg = *(const float4*)(g1 + h * HDd + dc);
        float4 bb = *(const float4*)(b1 + h * HDd + dc);
        float m = mu_s[t], r = rs_s[t];
        float* d = Qs + t * QS_STR + dc;
        d[0] = (v.x - m) * r * gg.x + bb.x;
        d[1] = (v.y - m) * r * gg.y + bb.y;
        d[2] = (v.z - m) * r * gg.z + bb.z;
        d[3] = (v.w - m) * r * gg.w + bb.w;
    }
    const float* kb = g_k + (size_t)b * Lt * Cch + h * HDd;
    const float* vb = g_v + (size_t)b * Lt * Cch + h * HDd;
    for (int f = tid; f < 80 * 16; f += 128) {
        int l = f >> 4, dc = (f & 15) << 2;
        float4 k4 = make_float4(0.f, 0.f, 0.f, 0.f), v4 = k4;
        if (l < Lt) {
            k4 = *(const float4*)(kb + (size_t)l * Cch + dc);
            v4 = *(const float4*)(vb + (size_t)l * Cch + dc);
        }
        float* kd = Ks + l * KS_STR + dc;
        kd[0] = k4.x; kd[1] = k4.y; kd[2] = k4.z; kd[3] = k4.w;
        float* vd = Vs + l * VS_STR + dc;
        vd[0] = v4.x; vd[1] = v4.y; vd[2] = v4.z; vd[3] = v4.w;
    }
    __syncthreads();

    const uint32_t* Qu = (const uint32_t*)Qs;
    const uint32_t* Ku = (const uint32_t*)Ks;
    const uint32_t* Vu = (const uint32_t*)Vs;

    // ---- S = Q K^T (64x80, K=64); warp w owns rows w*16 .. w*16+15
    float sfr[10][4] = {};
    #pragma unroll
    for (int ks = 0; ks < 8; ks++) {
        uint32_t aq[4];
        int ab = (w * 16 + g) * QS_STR + ks * 8 + tg;
        aq[0] = Qu[ab];
        aq[1] = Qu[ab + 8 * QS_STR];
        aq[2] = Qu[ab + 4];
        aq[3] = Qu[ab + 8 * QS_STR + 4];
        #pragma unroll
        for (int nt = 0; nt < 10; nt++) {
            uint32_t bf[2];
            int bb = (nt * 8 + g) * KS_STR + ks * 8 + tg;
            bf[0] = Ku[bb];
            bf[1] = Ku[bb + 4];
            mma8(sfr[nt], aq, bf);
        }
    }

    // ---- softmax over valid cols (<77); rows g (c0,c1) and g+8 (c2,c3)
    float mx0 = -1e30f, mx1 = -1e30f;
    #pragma unroll
    for (int nt = 0; nt < 10; nt++) {
        int c0 = nt * 8 + tg * 2, c1 = c0 + 1;
        if (c0 < Lt) { mx0 = fmaxf(mx0, sfr[nt][0]); mx1 = fmaxf(mx1, sfr[nt][2]); }
        if (c1 < Lt) { mx0 = fmaxf(mx0, sfr[nt][1]); mx1 = fmaxf(mx1, sfr[nt][3]); }
    }
    mx0 = fmaxf(mx0, __shfl_xor_sync(0xffffffffu, mx0, 1));
    mx0 = fmaxf(mx0, __shfl_xor_sync(0xffffffffu, mx0, 2));
    mx1 = fmaxf(mx1, __shfl_xor_sync(0xffffffffu, mx1, 1));
    mx1 = fmaxf(mx1, __shfl_xor_sync(0xffffffffu, mx1, 2));
    // note: sfr holds raw dot products; scale 0.125 applied here
    mx0 *= 0.125f; mx1 *= 0.125f;

    float sum0 = 0.f, sum1 = 0.f;
    float* prow0 = Ps + (w * 16 + g) * PS_STR;
    float* prow1 = Ps + (w * 16 + g + 8) * PS_STR;
    #pragma unroll
    for (int nt = 0; nt < 10; nt++) {
        int c0 = nt * 8 + tg * 2, c1 = c0 + 1;
        float e00 = (c0 < Lt) ? __expf(sfr[nt][0] * 0.125f - mx0) : 0.f;
        float e01 = (c1 < Lt) ? __expf(sfr[nt][1] * 0.125f - mx0) : 0.f;
        float e10 = (c0 < Lt) ? __expf(sfr[nt][2] * 0.125f - mx1) : 0.f;
        float e11 = (c1 < Lt) ? __expf(sfr[nt][3] * 0.125f - mx1) : 0.f;
        sum0 += e00 + e01; sum1 += e10 + e11;
        prow0[c0] = e00; prow0[c1] = e01;
        prow1[c0] = e10; prow1[c1] = e11;
    }
    sum0 += __shfl_xor_sync(0xffffffffu, sum0, 1);
    sum0 += __shfl_xor_sync(0xffffffffu, sum0, 2);
    sum1 += __shfl_xor_sync(0xffffffffu, sum1, 1);
    sum1 += __shfl_xor_sync(0xffffffffu, sum1, 2);
    float inv0 = 1.0f / sum0, inv1 = 1.0f / sum1;
    __syncwarp();

    // ---- O = P V (64x64, K=80)
    const uint32_t* Pu = (const uint32_t*)Ps;
    float ofr[8][4] = {};
    #pragma unroll
    for (int ks = 0; ks < 10; ks++) {
        uint32_t ap[4];
        int ab = (w * 16 + g) * PS_STR + ks * 8 + tg;
        ap[0] = Pu[ab];
        ap[1] = Pu[ab + 8 * PS_STR];
        ap[2] = Pu[ab + 4];
        ap[3] = Pu[ab + 8 * PS_STR + 4];
        #pragma unroll
        for (int nt = 0; nt < 8; nt++) {
            uint32_t bf[2];
            bf[0] = Vu[(ks * 8 + tg) * VS_STR + nt * 8 + g];
            bf[1] = Vu[(ks * 8 + tg + 4) * VS_STR + nt * 8 + g];
            mma8(ofr[nt], ap, bf);
        }
    }

    float* ob = g_attn + ((size_t)b * HWs + t0 + w * 16) * Cch + h * HDd;
    #pragma unroll
    for (int nt = 0; nt < 8; nt++) {
        int n = nt * 8 + tg * 2;
        float2 r0 = make_float2(ofr[nt][0] * inv0, ofr[nt][1] * inv0);
        float2 r1 = make_float2(ofr[nt][2] * inv1, ofr[nt][3] * inv1);
        *(float2*)(ob + (size_t)g * Cch + n) = r0;
        *(float2*)(ob + (size_t)(g + 8) * Cch + n) = r1;
    }
}

// =====================================================================
extern "C" void kernel_launch(void* const* d_in, const int* in_sizes, int n_in,
                              void* d_out, int out_size)
{
    const float* x  = (const float*)d_in[0];
    const float* tf = (const float*)d_in[1];
    const float* wq = (const float*)d_in[2];
    const float* bq = (const float*)d_in[3];
    const float* wk = (const float*)d_in[4];
    const float* bk = (const float*)d_in[5];
    const float* wv = (const float*)d_in[6];
    const float* bv = (const float*)d_in[7];
    const float* wo = (const float*)d_in[8];
    const float* bo = (const float*)d_in[9];
    const float* g1 = (const float*)d_in[10];
    const float* b1 = (const float*)d_in[11];
    const float* g2 = (const float*)d_in[12];
    const float* b2 = (const float*)d_in[13];
    float* out = (float*)d_out;

    const int gemm_smem = (2 * STAGE_A + 2 * STAGE_B) * 4;             // 73728 B
    const int qgemm_smem = (2 * STAGE_AQ + 2 * STAGE_B) * 4;           // 71680 B
    static int inited = 0;
    if (!inited) {
        cudaFuncSetAttribute(kv_proj_tc, cudaFuncAttributeMaxDynamicSharedMemorySize, gemm_smem);
        cudaFuncSetAttribute(o_proj_tc, cudaFuncAttributeMaxDynamicSharedMemorySize, gemm_smem);
        cudaFuncSetAttribute(q_proj_tc, cudaFuncAttributeMaxDynamicSharedMemorySize, qgemm_smem);
        cudaFuncSetAttribute(attn_tc, cudaFuncAttributeMaxDynamicSharedMemorySize, ATTN_SMEM);
        inited = 1;
    }

    kv_proj_tc<<<dim3(4, 10, 2), 256, gemm_smem>>>(tf, wk, bk, wv, bv);
    ln512_kernel<<<Bsz * Lt, 128>>>(g2, b2);
    q_proj_tc<<<dim3(4, 32, 16), 256, qgemm_smem>>>(x, wq, bq);
    ln_stats_kernel<<<Bsz * HWs / 8, 256>>>();
    attn_tc<<<dim3(64, 8, 16), 128, ATTN_SMEM>>>(g1, b1);
    o_proj_tc<<<dim3(32, 4, 16), 256, gemm_smem>>>(wo, bo, x, out);
}